// round 2
// baseline (speedup 1.0000x reference)
#include <cuda_runtime.h>
#include <cstdint>
#include <cstddef>

#define Nn 512
#define Cc 128
#define NPOS (Nn*Nn)
#define HP 132   // padded row for h/u (float4-aligned: 132*4=528, %16==0)
#define WP 133   // padded row for transposed weights (conflict-free scalar)

// ---------------- scratch (allocation-free: static device globals) ----------
__device__ __align__(256) float g_A[(size_t)NPOS * Cc];
__device__ __align__(256) float g_B[(size_t)NPOS * Cc];
__device__ __align__(256) float g_G[(size_t)NPOS * Cc];
__device__ __align__(256) float g_T[(size_t)NPOS * Cc];
__device__ int g_mask_mode;   // 0=int32, 1=uint8/bool, 2=float32

// ---------------- packed fp32x2 FMA (Blackwell FFMA2) -----------------------
typedef unsigned long long u64;
__device__ __forceinline__ u64 ffma2(u64 a, u64 b, u64 c) {
    u64 d;
    asm("fma.rn.f32x2 %0, %1, %2, %3;" : "=l"(d) : "l"(a), "l"(b), "l"(c));
    return d;
}

// ---------------- K0: mask dtype detection ----------------------------------
// mask comes from a jax bool array; depending on serialization it may arrive as
// int32 {0,1}, uint8 {0,1}, or float32 {0.0,1.0}. Distinguish by bit patterns
// over the first 4096 words (safe: smallest possible buffer is 256 KiB).
__global__ void kdetect(const unsigned int* __restrict__ mask) {
    __shared__ int flags[2];
    if (threadIdx.x < 2) flags[threadIdx.x] = 0;
    __syncthreads();
    for (int i = threadIdx.x; i < 4096; i += blockDim.x) {
        unsigned int v = mask[i];
        if (v == 0x3F800000u)      atomicOr(&flags[0], 1);  // float 1.0
        else if (v > 1u)           atomicOr(&flags[1], 1);  // byte-packed bools
    }
    __syncthreads();
    if (threadIdx.x == 0)
        g_mask_mode = flags[0] ? 2 : (flags[1] ? 1 : 0);
}

// ---------------- shared 128x128 linear layer (M=32 tokens) -----------------
// thread tid = output channel n; acc over 32 tokens; W transposed in smem.
template<bool SIG, bool MASK, bool GMUL, bool OUT_S, bool OUT_G>
__device__ __forceinline__ void lin128(
    const float* __restrict__ in_s,      // smem [32][HP]
    float* __restrict__ Wt,              // smem [128][WP]
    const float* __restrict__ Wg,        // global (out,in) row-major
    const float* __restrict__ bg,        // global bias
    float* __restrict__ out_s,           // smem [32][HP] (if OUT_S)
    float* __restrict__ out_g,           // global channel-last (if OUT_G)
    const float* __restrict__ msk,       // smem [32] (if MASK)
    const float* __restrict__ gmul,      // global channel-last (if GMUL)
    int t0)
{
    const int tid = threadIdx.x;
    // load transposed weights: Wt[k][n] = W[n][k]
    #pragma unroll 4
    for (int idx = tid; idx < Cc * Cc; idx += 128) {
        int n = idx >> 7, k = idx & 127;
        Wt[k * WP + n] = Wg[idx];
    }
    __syncthreads();

    float acc[32];
    #pragma unroll
    for (int m = 0; m < 32; ++m) acc[m] = 0.f;

    for (int k = 0; k < Cc; k += 4) {
        const float w0 = Wt[(k + 0) * WP + tid];
        const float w1 = Wt[(k + 1) * WP + tid];
        const float w2 = Wt[(k + 2) * WP + tid];
        const float w3 = Wt[(k + 3) * WP + tid];
        #pragma unroll
        for (int m = 0; m < 32; ++m) {
            const float4 hv = *reinterpret_cast<const float4*>(in_s + m * HP + k);
            acc[m] = fmaf(hv.w, w3, fmaf(hv.z, w2, fmaf(hv.y, w1, fmaf(hv.x, w0, acc[m]))));
        }
    }

    const float b = bg[tid];
    #pragma unroll
    for (int m = 0; m < 32; ++m) {
        float v = acc[m] + b;
        if (SIG)  v = 1.f / (1.f + __expf(-v));
        if (MASK) v *= msk[m];
        if (GMUL) v *= gmul[(size_t)(t0 + m) * Cc + tid];
        if (OUT_S) out_s[m * HP + tid] = v;
        if (OUT_G) out_g[(size_t)(t0 + m) * Cc + tid] = v;
    }
    __syncthreads();
}

// ---------------- K1: LN1 + edge MLPs + gate ---------------------------------
__global__ __launch_bounds__(128, 2) void k1_kernel(
    const float* __restrict__ X, const void* __restrict__ mask,
    const float* __restrict__ ln1g, const float* __restrict__ ln1b,
    const float* __restrict__ lw1, const float* __restrict__ lb1,
    const float* __restrict__ lw2, const float* __restrict__ lb2,
    const float* __restrict__ rw1, const float* __restrict__ rb1,
    const float* __restrict__ rw2, const float* __restrict__ rb2,
    const float* __restrict__ sw_, const float* __restrict__ sb_)
{
    extern __shared__ float smem[];
    float* h  = smem;                  // [32][HP]
    float* u  = smem + 32 * HP;        // [32][HP]
    float* Wt = smem + 2 * 32 * HP;    // [128][WP]
    __shared__ float msk[32];

    const int tid = threadIdx.x;
    const int t0  = blockIdx.x * 32;

    // load X tile
    #pragma unroll 4
    for (int idx = tid; idx < 32 * Cc; idx += 128) {
        int m = idx >> 7, c = idx & 127;
        h[m * HP + c] = X[(size_t)(t0 + m) * Cc + c];
    }
    // mask values (dtype-dispatch via detected mode)
    if (tid < 32) {
        const int mode = g_mask_mode;
        const int t = t0 + tid;
        float mv;
        if (mode == 0)      mv = (((const int*)mask)[t] != 0) ? 1.f : 0.f;
        else if (mode == 1) mv = (((const unsigned char*)mask)[t] != 0) ? 1.f : 0.f;
        else                mv = (((const float*)mask)[t] != 0.f) ? 1.f : 0.f;
        msk[tid] = mv;
    }
    __syncthreads();

    // LayerNorm in place: 4 threads per token
    {
        const int m = tid >> 2, s = tid & 3;
        float sum = 0.f, sq = 0.f;
        for (int c = s; c < Cc; c += 4) {
            float v = h[m * HP + c];
            sum += v; sq += v * v;
        }
        sum += __shfl_xor_sync(0xffffffffu, sum, 1);
        sq  += __shfl_xor_sync(0xffffffffu, sq , 1);
        sum += __shfl_xor_sync(0xffffffffu, sum, 2);
        sq  += __shfl_xor_sync(0xffffffffu, sq , 2);
        const float mu  = sum * (1.f / Cc);
        const float var = sq * (1.f / Cc) - mu * mu;
        const float rs  = rsqrtf(var + 1e-5f);
        for (int c = s; c < Cc; c += 4) {
            float v = h[m * HP + c];
            h[m * HP + c] = (v - mu) * rs * ln1g[c] + ln1b[c];
        }
    }
    __syncthreads();

    // left edge:  u = sigmoid(h@lw1^T+lb1); A = mask*(u@lw2^T+lb2)
    lin128<true , false, false, true , false>(h, Wt, lw1, lb1, u, nullptr, nullptr, nullptr, t0);
    lin128<false, true , false, false, true >(u, Wt, lw2, lb2, nullptr, g_A, msk, nullptr, t0);
    // right edge
    lin128<true , false, false, true , false>(h, Wt, rw1, rb1, u, nullptr, nullptr, nullptr, t0);
    lin128<false, true , false, false, true >(u, Wt, rw2, rb2, nullptr, g_B, msk, nullptr, t0);
    // skip gate
    lin128<true , false, false, false, true >(h, Wt, sw_, sb_, nullptr, g_G, nullptr, nullptr, t0);
}

// ---------------- K2: triangle einsum, packed f32x2 --------------------------
// T[i,j,c] = sum_k A[i,k,c] * B[j,k,c]. Channel pair per thread (perfect f32x2
// fit). Block (64,2,2) covers a 16x16 (i,j) tile across all 128 channels;
// thread tile 8x8 pairs. 8x8 block supertiles keep A/B bands L2-resident.
__global__ __launch_bounds__(256, 1) void k2_kernel()
{
    const int cp = threadIdx.x;                 // channel pair 0..63
    const int ty = threadIdx.y, tz = threadIdx.z;

    const int sb  = blockIdx.x;                 // 0..1023
    const int st  = sb >> 6, w = sb & 63;       // 16 supertiles of 64 blocks
    const int sti = st >> 2, stj = st & 3;      // 4x4 supertile grid
    const int bi  = sti * 8 + (w >> 3);
    const int bj  = stj * 8 + (w & 7);
    const int i0  = bi * 16 + ty * 8;
    const int j0  = bj * 16 + tz * 8;

    const u64* __restrict__ A2 = reinterpret_cast<const u64*>(g_A);
    const u64* __restrict__ B2 = reinterpret_cast<const u64*>(g_B);

    u64 acc[8][8];
    const u64 z = 0ull;
    #pragma unroll
    for (int ii = 0; ii < 8; ++ii)
        #pragma unroll
        for (int jj = 0; jj < 8; ++jj) acc[ii][jj] = z;

    const u64* ap = A2 + (size_t)i0 * Nn * 64 + cp;
    const u64* bp = B2 + (size_t)j0 * Nn * 64 + cp;

    for (int k = 0; k < Nn; ++k) {
        u64 a[8], b[8];
        #pragma unroll
        for (int ii = 0; ii < 8; ++ii) a[ii] = ap[(size_t)ii * Nn * 64 + (size_t)k * 64];
        #pragma unroll
        for (int jj = 0; jj < 8; ++jj) b[jj] = bp[(size_t)jj * Nn * 64 + (size_t)k * 64];
        #pragma unroll
        for (int ii = 0; ii < 8; ++ii)
            #pragma unroll
            for (int jj = 0; jj < 8; ++jj)
                acc[ii][jj] = ffma2(a[ii], b[jj], acc[ii][jj]);
    }

    u64* __restrict__ T2 = reinterpret_cast<u64*>(g_T);
    #pragma unroll
    for (int ii = 0; ii < 8; ++ii)
        #pragma unroll
        for (int jj = 0; jj < 8; ++jj)
            T2[((size_t)(i0 + ii) * Nn + (j0 + jj)) * 64 + cp] = acc[ii][jj];
}

// ---------------- K3: LN2 + combine linear + gate ----------------------------
__global__ __launch_bounds__(128, 2) void k3_kernel(
    const float* __restrict__ ln2g, const float* __restrict__ ln2b,
    const float* __restrict__ cw, const float* __restrict__ cb,
    float* __restrict__ Y)
{
    extern __shared__ float smem[];
    float* h  = smem;               // [32][HP]
    float* Wt = smem + 32 * HP;     // [128][WP]

    const int tid = threadIdx.x;
    const int t0  = blockIdx.x * 32;

    #pragma unroll 4
    for (int idx = tid; idx < 32 * Cc; idx += 128) {
        int m = idx >> 7, c = idx & 127;
        h[m * HP + c] = g_T[(size_t)(t0 + m) * Cc + c];
    }
    __syncthreads();

    {
        const int m = tid >> 2, s = tid & 3;
        float sum = 0.f, sq = 0.f;
        for (int c = s; c < Cc; c += 4) {
            float v = h[m * HP + c];
            sum += v; sq += v * v;
        }
        sum += __shfl_xor_sync(0xffffffffu, sum, 1);
        sq  += __shfl_xor_sync(0xffffffffu, sq , 1);
        sum += __shfl_xor_sync(0xffffffffu, sum, 2);
        sq  += __shfl_xor_sync(0xffffffffu, sq , 2);
        const float mu  = sum * (1.f / Cc);
        const float var = sq * (1.f / Cc) - mu * mu;
        const float rs  = rsqrtf(var + 1e-5f);
        for (int c = s; c < Cc; c += 4) {
            float v = h[m * HP + c];
            h[m * HP + c] = (v - mu) * rs * ln2g[c] + ln2b[c];
        }
    }
    __syncthreads();

    // Y = (LN(T) @ cw^T + cb) * G
    lin128<false, false, true, false, true>(h, Wt, cw, cb, nullptr, Y, nullptr, g_G, t0);
}

// ---------------- launch ------------------------------------------------------
extern "C" void kernel_launch(void* const* d_in, const int* in_sizes, int n_in,
                              void* d_out, int out_size)
{
    (void)in_sizes; (void)n_in; (void)out_size;
    const float* X    = (const float*)d_in[0];
    const void*  mask = d_in[1];
    const float* ln1g = (const float*)d_in[2];
    const float* ln1b = (const float*)d_in[3];
    const float* lw1  = (const float*)d_in[4];
    const float* lb1  = (const float*)d_in[5];
    const float* lw2  = (const float*)d_in[6];
    const float* lb2  = (const float*)d_in[7];
    const float* rw1  = (const float*)d_in[8];
    const float* rb1  = (const float*)d_in[9];
    const float* rw2  = (const float*)d_in[10];
    const float* rb2  = (const float*)d_in[11];
    const float* sw_  = (const float*)d_in[12];
    const float* sb_  = (const float*)d_in[13];
    const float* ln2g = (const float*)d_in[14];
    const float* ln2b = (const float*)d_in[15];
    const float* cw   = (const float*)d_in[16];
    const float* cb   = (const float*)d_in[17];
    float* Y = (float*)d_out;

    const int smem1 = (2 * 32 * HP + Cc * WP) * (int)sizeof(float);
    const int smem3 = (32 * HP + Cc * WP) * (int)sizeof(float);
    cudaFuncSetAttribute(k1_kernel, cudaFuncAttributeMaxDynamicSharedMemorySize, smem1);
    cudaFuncSetAttribute(k3_kernel, cudaFuncAttributeMaxDynamicSharedMemorySize, smem3);

    kdetect<<<1, 256>>>((const unsigned int*)mask);
    k1_kernel<<<NPOS / 32, 128, smem1>>>(X, mask, ln1g, ln1b, lw1, lb1, lw2, lb2,
                                         rw1, rb1, rw2, rb2, sw_, sb_);
    dim3 b2(64, 2, 2);
    k2_kernel<<<1024, b2>>>();
    k3_kernel<<<NPOS / 32, 128, smem3>>>(ln2g, ln2b, cw, cb, Y);
}

// round 3
// speedup vs baseline: 1.6738x; 1.6738x over previous
#include <cuda_runtime.h>
#include <cstdint>
#include <cstddef>

#define Nn 512
#define Cc 128
#define NPOS (Nn*Nn)
#define HP 132     // padded fp32 row for token tiles (16B-aligned rows)
#define WROW 66    // padded u64 row for packed weights (132 floats)

typedef unsigned long long u64;

// ---------------- scratch (allocation-free: static device globals) ----------
__device__ __align__(256) float g_A[(size_t)NPOS * Cc];
__device__ __align__(256) float g_B[(size_t)NPOS * Cc];
__device__ __align__(256) float g_G[(size_t)NPOS * Cc];
__device__ __align__(256) float g_T[(size_t)NPOS * Cc];
__device__ int g_mask_mode;   // 0=int32, 1=uint8/bool, 2=float32

// ---------------- packed fp32x2 helpers (Blackwell FFMA2) -------------------
__device__ __forceinline__ u64 ffma2(u64 a, u64 b, u64 c) {
    u64 d;
    asm("fma.rn.f32x2 %0, %1, %2, %3;" : "=l"(d) : "l"(a), "l"(b), "l"(c));
    return d;
}
__device__ __forceinline__ u64 mul2(u64 a, u64 b) {
    u64 d;
    asm("mul.rn.f32x2 %0, %1, %2;" : "=l"(d) : "l"(a), "l"(b));
    return d;
}
__device__ __forceinline__ u64 pack2(float x) {
    u64 r;
    asm("mov.b64 %0, {%1, %1};" : "=l"(r) : "f"(x));
    return r;
}
__device__ __forceinline__ u64 pack2two(float lo, float hi) {
    u64 r;
    asm("mov.b64 %0, {%1, %2};" : "=l"(r) : "f"(lo), "f"(hi));
    return r;
}
__device__ __forceinline__ void unpack2(u64 v, float& lo, float& hi) {
    asm("mov.b64 {%0, %1}, %2;" : "=f"(lo), "=f"(hi) : "l"(v));
}
__device__ __forceinline__ float sigf(float x) {
    return 1.f / (1.f + __expf(-x));
}

// ---------------- K0: mask dtype detection ----------------------------------
__global__ void kdetect(const unsigned int* __restrict__ mask) {
    __shared__ int flags[2];
    if (threadIdx.x < 2) flags[threadIdx.x] = 0;
    __syncthreads();
    for (int i = threadIdx.x; i < 4096; i += blockDim.x) {
        unsigned int v = mask[i];
        if (v == 0x3F800000u)      atomicOr(&flags[0], 1);  // float 1.0
        else if (v > 1u)           atomicOr(&flags[1], 1);  // byte-packed bools
    }
    __syncthreads();
    if (threadIdx.x == 0)
        g_mask_mode = flags[0] ? 2 : (flags[1] ? 1 : 0);
}

// ---------------- packed-f32x2 128x128 linear over M=128 tokens -------------
// 256 threads; thread (tx,ty): tx = channel-pair quad (4 u64 = 8 channels),
// ty = token group (8 tokens). 32 u64 accumulators per thread.
template<bool SIG, bool MASK, bool GMUL, bool OUT_S, bool OUT_G>
__device__ __forceinline__ void lin128x2(
    const float* __restrict__ in_s,    // smem [128][HP]
    u64* __restrict__ Wt2,             // smem [128][WROW] packed pairs
    const float* __restrict__ Wg,      // global (out,in) row-major
    const float* __restrict__ bg,      // global bias
    float* __restrict__ out_s,         // smem [128][HP] (if OUT_S)
    u64* __restrict__ out_g,           // global channel-last, u64 view (if OUT_G)
    const float* __restrict__ msk,     // smem [128] (if MASK)
    const u64* __restrict__ gmul,      // global channel-last u64 view (if GMUL)
    int t0)
{
    const int t = threadIdx.x;

    // stage packed-transposed weights: Wt2f[k][n] = W[n][k], pairs contiguous
    {
        const int n = t >> 1, half = t & 1;
        const float4* wrow = reinterpret_cast<const float4*>(Wg + n * Cc + half * 64);
        float* dst = reinterpret_cast<float*>(Wt2);
        #pragma unroll
        for (int q = 0; q < 16; ++q) {
            float4 v = wrow[q];
            int kb = half * 64 + q * 4;
            dst[(size_t)(kb + 0) * (2 * WROW) + n] = v.x;
            dst[(size_t)(kb + 1) * (2 * WROW) + n] = v.y;
            dst[(size_t)(kb + 2) * (2 * WROW) + n] = v.z;
            dst[(size_t)(kb + 3) * (2 * WROW) + n] = v.w;
        }
    }
    __syncthreads();

    const int tx = t & 15, ty = t >> 4;
    const float* hbase = in_s + (size_t)ty * 8 * HP;
    const u64*   wbase = Wt2 + tx * 4;

    u64 acc[8][4];
    {
        const u64* b2 = reinterpret_cast<const u64*>(bg) + tx * 4;
        u64 b[4];
        #pragma unroll
        for (int j = 0; j < 4; ++j) b[j] = b2[j];
        #pragma unroll
        for (int i = 0; i < 8; ++i)
            #pragma unroll
            for (int j = 0; j < 4; ++j) acc[i][j] = b[j];
    }

    #pragma unroll 2
    for (int k4 = 0; k4 < 32; ++k4) {
        float4 a4[8];
        #pragma unroll
        for (int i = 0; i < 8; ++i)
            a4[i] = *reinterpret_cast<const float4*>(hbase + i * HP + k4 * 4);
        #pragma unroll
        for (int kk = 0; kk < 4; ++kk) {
            u64 w[4];
            const u64* wr = wbase + (size_t)(k4 * 4 + kk) * WROW;
            #pragma unroll
            for (int j = 0; j < 4; ++j) w[j] = wr[j];
            #pragma unroll
            for (int i = 0; i < 8; ++i) {
                float av = (kk == 0) ? a4[i].x : (kk == 1) ? a4[i].y
                         : (kk == 2) ? a4[i].z : a4[i].w;
                u64 ap = pack2(av);
                #pragma unroll
                for (int j = 0; j < 4; ++j)
                    acc[i][j] = ffma2(ap, w[j], acc[i][j]);
            }
        }
    }

    #pragma unroll
    for (int i = 0; i < 8; ++i) {
        const int tok = ty * 8 + i;
        u64 mp = 0;
        if (MASK) mp = pack2(msk[tok]);
        #pragma unroll
        for (int j = 0; j < 4; ++j) {
            u64 v = acc[i][j];
            if (SIG) {
                float lo, hi; unpack2(v, lo, hi);
                v = pack2two(sigf(lo), sigf(hi));
            }
            if (MASK) v = mul2(v, mp);
            if (GMUL) v = mul2(v, gmul[(size_t)(t0 + tok) * 64 + tx * 4 + j]);
            if (OUT_S)
                *reinterpret_cast<u64*>(out_s + (size_t)tok * HP + tx * 8 + j * 2) = v;
            if (OUT_G)
                out_g[(size_t)(t0 + tok) * 64 + tx * 4 + j] = v;
        }
    }
    __syncthreads();
}

// ---------------- shared LayerNorm over 128 tokens (256 threads) ------------
__device__ __forceinline__ void ln128(
    float* __restrict__ h,             // smem [128][HP], in place
    const float* __restrict__ g, const float* __restrict__ b)
{
    const int t = threadIdx.x;
    const int m = t >> 1, s = t & 1;
    float* row = h + (size_t)m * HP + s * 64;
    float sum = 0.f, sq = 0.f;
    #pragma unroll
    for (int q = 0; q < 16; ++q) {
        float4 v = *reinterpret_cast<const float4*>(row + q * 4);
        sum += v.x + v.y + v.z + v.w;
        sq  += v.x * v.x + v.y * v.y + v.z * v.z + v.w * v.w;
    }
    sum += __shfl_xor_sync(0xffffffffu, sum, 1);
    sq  += __shfl_xor_sync(0xffffffffu, sq , 1);
    const float mu  = sum * (1.f / Cc);
    const float var = sq * (1.f / Cc) - mu * mu;
    const float rs  = rsqrtf(var + 1e-5f);
    #pragma unroll
    for (int q = 0; q < 16; ++q) {
        float4 v = *reinterpret_cast<float4*>(row + q * 4);
        const int c = s * 64 + q * 4;
        v.x = (v.x - mu) * rs * g[c + 0] + b[c + 0];
        v.y = (v.y - mu) * rs * g[c + 1] + b[c + 1];
        v.z = (v.z - mu) * rs * g[c + 2] + b[c + 2];
        v.w = (v.w - mu) * rs * g[c + 3] + b[c + 3];
        *reinterpret_cast<float4*>(row + q * 4) = v;
    }
}

// ---------------- K1: LN1 + edge MLPs + gate ---------------------------------
__global__ __launch_bounds__(256, 1) void k1_kernel(
    const float* __restrict__ X, const void* __restrict__ mask,
    const float* __restrict__ ln1g, const float* __restrict__ ln1b,
    const float* __restrict__ lw1, const float* __restrict__ lb1,
    const float* __restrict__ lw2, const float* __restrict__ lb2,
    const float* __restrict__ rw1, const float* __restrict__ rb1,
    const float* __restrict__ rw2, const float* __restrict__ rb2,
    const float* __restrict__ sw_, const float* __restrict__ sb_)
{
    extern __shared__ float smem[];
    float* h   = smem;                         // [128][HP]
    float* u   = smem + 128 * HP;              // [128][HP]
    u64*   Wt2 = reinterpret_cast<u64*>(smem + 2 * 128 * HP);  // [128][WROW]
    __shared__ float msk[128];

    const int t  = threadIdx.x;
    const int t0 = blockIdx.x * 128;

    // load X tile (128x128) as float4, coalesced
    {
        const float4* X4 = reinterpret_cast<const float4*>(X + (size_t)t0 * Cc);
        #pragma unroll
        for (int r = 0; r < 16; ++r) {
            int idx = t + r * 256;
            int m = idx >> 5, q = idx & 31;
            *reinterpret_cast<float4*>(h + (size_t)m * HP + q * 4) = X4[idx];
        }
    }
    if (t < 128) {
        const int mode = g_mask_mode;
        const int tk = t0 + t;
        float mv;
        if (mode == 0)      mv = (((const int*)mask)[tk] != 0) ? 1.f : 0.f;
        else if (mode == 1) mv = (((const unsigned char*)mask)[tk] != 0) ? 1.f : 0.f;
        else                mv = (((const float*)mask)[tk] != 0.f) ? 1.f : 0.f;
        msk[t] = mv;
    }
    __syncthreads();

    ln128(h, ln1g, ln1b);
    __syncthreads();

    u64* gA = reinterpret_cast<u64*>(g_A);
    u64* gB = reinterpret_cast<u64*>(g_B);
    u64* gG = reinterpret_cast<u64*>(g_G);

    // left edge: u = sigmoid(h@lw1^T+lb1); A = mask*(u@lw2^T+lb2)
    lin128x2<true , false, false, true , false>(h, Wt2, lw1, lb1, u, nullptr, nullptr, nullptr, t0);
    lin128x2<false, true , false, false, true >(u, Wt2, lw2, lb2, nullptr, gA, msk, nullptr, t0);
    // right edge
    lin128x2<true , false, false, true , false>(h, Wt2, rw1, rb1, u, nullptr, nullptr, nullptr, t0);
    lin128x2<false, true , false, false, true >(u, Wt2, rw2, rb2, nullptr, gB, msk, nullptr, t0);
    // skip gate
    lin128x2<true , false, false, false, true >(h, Wt2, sw_, sb_, nullptr, gG, nullptr, nullptr, t0);
}

// ---------------- K2: triangle einsum, packed f32x2 --------------------------
__global__ __launch_bounds__(256, 1) void k2_kernel()
{
    const int cp = threadIdx.x;                 // channel pair 0..63
    const int ty = threadIdx.y, tz = threadIdx.z;

    const int sb  = blockIdx.x;                 // 0..1023
    const int st  = sb >> 6, w = sb & 63;       // 16 supertiles of 64 blocks
    const int sti = st >> 2, stj = st & 3;      // 4x4 supertile grid
    const int bi  = sti * 8 + (w >> 3);
    const int bj  = stj * 8 + (w & 7);
    const int i0  = bi * 16 + ty * 8;
    const int j0  = bj * 16 + tz * 8;

    const u64* __restrict__ A2 = reinterpret_cast<const u64*>(g_A);
    const u64* __restrict__ B2 = reinterpret_cast<const u64*>(g_B);

    u64 acc[8][8];
    #pragma unroll
    for (int ii = 0; ii < 8; ++ii)
        #pragma unroll
        for (int jj = 0; jj < 8; ++jj) acc[ii][jj] = 0ull;

    const u64* ap = A2 + (size_t)i0 * Nn * 64 + cp;
    const u64* bp = B2 + (size_t)j0 * Nn * 64 + cp;

    for (int k = 0; k < Nn; ++k) {
        u64 a[8], b[8];
        #pragma unroll
        for (int ii = 0; ii < 8; ++ii) a[ii] = ap[(size_t)ii * Nn * 64 + (size_t)k * 64];
        #pragma unroll
        for (int jj = 0; jj < 8; ++jj) b[jj] = bp[(size_t)jj * Nn * 64 + (size_t)k * 64];
        #pragma unroll
        for (int ii = 0; ii < 8; ++ii)
            #pragma unroll
            for (int jj = 0; jj < 8; ++jj)
                acc[ii][jj] = ffma2(a[ii], b[jj], acc[ii][jj]);
    }

    u64* __restrict__ T2 = reinterpret_cast<u64*>(g_T);
    #pragma unroll
    for (int ii = 0; ii < 8; ++ii)
        #pragma unroll
        for (int jj = 0; jj < 8; ++jj)
            T2[((size_t)(i0 + ii) * Nn + (j0 + jj)) * 64 + cp] = acc[ii][jj];
}

// ---------------- K3: LN2 + combine linear + gate ----------------------------
__global__ __launch_bounds__(256, 1) void k3_kernel(
    const float* __restrict__ ln2g, const float* __restrict__ ln2b,
    const float* __restrict__ cw, const float* __restrict__ cb,
    float* __restrict__ Y)
{
    extern __shared__ float smem[];
    float* h   = smem;                                  // [128][HP]
    u64*   Wt2 = reinterpret_cast<u64*>(smem + 128 * HP);

    const int t  = threadIdx.x;
    const int t0 = blockIdx.x * 128;

    {
        const float4* T4 = reinterpret_cast<const float4*>(g_T + (size_t)t0 * Cc);
        #pragma unroll
        for (int r = 0; r < 16; ++r) {
            int idx = t + r * 256;
            int m = idx >> 5, q = idx & 31;
            *reinterpret_cast<float4*>(h + (size_t)m * HP + q * 4) = T4[idx];
        }
    }
    __syncthreads();

    ln128(h, ln2g, ln2b);
    __syncthreads();

    // Y = (LN(T) @ cw^T + cb) * G
    lin128x2<false, false, true, false, true>(
        h, Wt2, cw, cb, nullptr, reinterpret_cast<u64*>(Y), nullptr,
        reinterpret_cast<const u64*>(g_G), t0);
}

// ---------------- launch ------------------------------------------------------
extern "C" void kernel_launch(void* const* d_in, const int* in_sizes, int n_in,
                              void* d_out, int out_size)
{
    (void)in_sizes; (void)n_in; (void)out_size;
    const float* X    = (const float*)d_in[0];
    const void*  mask = d_in[1];
    const float* ln1g = (const float*)d_in[2];
    const float* ln1b = (const float*)d_in[3];
    const float* lw1  = (const float*)d_in[4];
    const float* lb1  = (const float*)d_in[5];
    const float* lw2  = (const float*)d_in[6];
    const float* lb2  = (const float*)d_in[7];
    const float* rw1  = (const float*)d_in[8];
    const float* rb1  = (const float*)d_in[9];
    const float* rw2  = (const float*)d_in[10];
    const float* rb2  = (const float*)d_in[11];
    const float* sw_  = (const float*)d_in[12];
    const float* sb_  = (const float*)d_in[13];
    const float* ln2g = (const float*)d_in[14];
    const float* ln2b = (const float*)d_in[15];
    const float* cw   = (const float*)d_in[16];
    const float* cb   = (const float*)d_in[17];
    float* Y = (float*)d_out;

    const int smem1 = (2 * 128 * HP) * 4 + 128 * WROW * 8;   // 202752 B
    const int smem3 = (128 * HP) * 4 + 128 * WROW * 8;       // 135168 B
    cudaFuncSetAttribute(k1_kernel, cudaFuncAttributeMaxDynamicSharedMemorySize, smem1);
    cudaFuncSetAttribute(k3_kernel, cudaFuncAttributeMaxDynamicSharedMemorySize, smem3);

    kdetect<<<1, 256>>>((const unsigned int*)mask);
    k1_kernel<<<NPOS / 128, 256, smem1>>>(X, mask, ln1g, ln1b, lw1, lb1, lw2, lb2,
                                          rw1, rb1, rw2, rb2, sw_, sb_);
    dim3 b2(64, 2, 2);
    k2_kernel<<<1024, b2>>>();
    k3_kernel<<<NPOS / 128, 256, smem3>>>(ln2g, ln2b, cw, cb, Y);
}

// round 4
// speedup vs baseline: 1.6743x; 1.0003x over previous
#include <cuda_runtime.h>
#include <cstdint>
#include <cstddef>

#define Nn 512
#define Cc 128
#define NPOS (Nn*Nn)
#define HP 132     // padded fp32 row for token tiles (16B-aligned rows)
#define WROW 66    // padded u64 row for packed weights (132 floats)

typedef unsigned long long u64;

// ---------------- scratch (allocation-free: static device globals) ----------
__device__ __align__(256) float g_A[(size_t)NPOS * Cc];
__device__ __align__(256) float g_B[(size_t)NPOS * Cc];
__device__ __align__(256) float g_G[(size_t)NPOS * Cc];
__device__ __align__(256) float g_T[(size_t)NPOS * Cc];
__device__ int g_mask_mode;   // 0=int32, 1=uint8/bool, 2=float32

// ---------------- packed fp32x2 helpers (Blackwell FFMA2) -------------------
__device__ __forceinline__ u64 ffma2(u64 a, u64 b, u64 c) {
    u64 d;
    asm("fma.rn.f32x2 %0, %1, %2, %3;" : "=l"(d) : "l"(a), "l"(b), "l"(c));
    return d;
}
__device__ __forceinline__ u64 mul2(u64 a, u64 b) {
    u64 d;
    asm("mul.rn.f32x2 %0, %1, %2;" : "=l"(d) : "l"(a), "l"(b));
    return d;
}
__device__ __forceinline__ u64 pack2(float x) {
    u64 r;
    asm("mov.b64 %0, {%1, %1};" : "=l"(r) : "f"(x));
    return r;
}
__device__ __forceinline__ u64 pack2two(float lo, float hi) {
    u64 r;
    asm("mov.b64 %0, {%1, %2};" : "=l"(r) : "f"(lo), "f"(hi));
    return r;
}
__device__ __forceinline__ void unpack2(u64 v, float& lo, float& hi) {
    asm("mov.b64 {%0, %1}, %2;" : "=f"(lo), "=f"(hi) : "l"(v));
}
__device__ __forceinline__ float sigf(float x) {
    return 1.f / (1.f + __expf(-x));
}

// ---------------- K0: mask dtype detection ----------------------------------
__global__ void kdetect(const unsigned int* __restrict__ mask) {
    __shared__ int flags[2];
    if (threadIdx.x < 2) flags[threadIdx.x] = 0;
    __syncthreads();
    for (int i = threadIdx.x; i < 4096; i += blockDim.x) {
        unsigned int v = mask[i];
        if (v == 0x3F800000u)      atomicOr(&flags[0], 1);  // float 1.0
        else if (v > 1u)           atomicOr(&flags[1], 1);  // byte-packed bools
    }
    __syncthreads();
    if (threadIdx.x == 0)
        g_mask_mode = flags[0] ? 2 : (flags[1] ? 1 : 0);
}

// ---------------- packed-f32x2 128x128 linear over M=128 tokens -------------
// 256 threads; thread (tx,ty): tx = channel-pair quad (4 u64 = 8 channels),
// ty = token group (8 tokens). 32 u64 accumulators per thread.
template<bool SIG, bool MASK, bool GMUL, bool OUT_S, bool OUT_G>
__device__ __forceinline__ void lin128x2(
    const float* __restrict__ in_s,    // smem [128][HP]
    u64* __restrict__ Wt2,             // smem [128][WROW] packed pairs
    const float* __restrict__ Wg,      // global (out,in) row-major
    const float* __restrict__ bg,      // global bias
    float* __restrict__ out_s,         // smem [128][HP] (if OUT_S)
    u64* __restrict__ out_g,           // global channel-last, u64 view (if OUT_G)
    const float* __restrict__ msk,     // smem [128] (if MASK)
    const u64* __restrict__ gmul,      // global channel-last u64 view (if GMUL)
    int t0)
{
    const int t = threadIdx.x;

    // stage packed-transposed weights: Wt2f[k][n] = W[n][k], pairs contiguous
    {
        const int n = t >> 1, half = t & 1;
        const float4* wrow = reinterpret_cast<const float4*>(Wg + n * Cc + half * 64);
        float* dst = reinterpret_cast<float*>(Wt2);
        #pragma unroll
        for (int q = 0; q < 16; ++q) {
            float4 v = wrow[q];
            int kb = half * 64 + q * 4;
            dst[(size_t)(kb + 0) * (2 * WROW) + n] = v.x;
            dst[(size_t)(kb + 1) * (2 * WROW) + n] = v.y;
            dst[(size_t)(kb + 2) * (2 * WROW) + n] = v.z;
            dst[(size_t)(kb + 3) * (2 * WROW) + n] = v.w;
        }
    }
    __syncthreads();

    const int tx = t & 15, ty = t >> 4;
    const float* hbase = in_s + (size_t)ty * 8 * HP;
    const u64*   wbase = Wt2 + tx * 4;

    u64 acc[8][4];
    {
        const u64* b2 = reinterpret_cast<const u64*>(bg) + tx * 4;
        u64 b[4];
        #pragma unroll
        for (int j = 0; j < 4; ++j) b[j] = b2[j];
        #pragma unroll
        for (int i = 0; i < 8; ++i)
            #pragma unroll
            for (int j = 0; j < 4; ++j) acc[i][j] = b[j];
    }

    #pragma unroll 2
    for (int k4 = 0; k4 < 32; ++k4) {
        float4 a4[8];
        #pragma unroll
        for (int i = 0; i < 8; ++i)
            a4[i] = *reinterpret_cast<const float4*>(hbase + i * HP + k4 * 4);
        #pragma unroll
        for (int kk = 0; kk < 4; ++kk) {
            u64 w[4];
            const u64* wr = wbase + (size_t)(k4 * 4 + kk) * WROW;
            #pragma unroll
            for (int j = 0; j < 4; ++j) w[j] = wr[j];
            #pragma unroll
            for (int i = 0; i < 8; ++i) {
                float av = (kk == 0) ? a4[i].x : (kk == 1) ? a4[i].y
                         : (kk == 2) ? a4[i].z : a4[i].w;
                u64 ap = pack2(av);
                #pragma unroll
                for (int j = 0; j < 4; ++j)
                    acc[i][j] = ffma2(ap, w[j], acc[i][j]);
            }
        }
    }

    #pragma unroll
    for (int i = 0; i < 8; ++i) {
        const int tok = ty * 8 + i;
        u64 mp = 0;
        if (MASK) mp = pack2(msk[tok]);
        #pragma unroll
        for (int j = 0; j < 4; ++j) {
            u64 v = acc[i][j];
            if (SIG) {
                float lo, hi; unpack2(v, lo, hi);
                v = pack2two(sigf(lo), sigf(hi));
            }
            if (MASK) v = mul2(v, mp);
            if (GMUL) v = mul2(v, gmul[(size_t)(t0 + tok) * 64 + tx * 4 + j]);
            if (OUT_S)
                *reinterpret_cast<u64*>(out_s + (size_t)tok * HP + tx * 8 + j * 2) = v;
            if (OUT_G)
                out_g[(size_t)(t0 + tok) * 64 + tx * 4 + j] = v;
        }
    }
    __syncthreads();
}

// ---------------- shared LayerNorm over 128 tokens (256 threads) ------------
__device__ __forceinline__ void ln128(
    float* __restrict__ h,             // smem [128][HP], in place
    const float* __restrict__ g, const float* __restrict__ b)
{
    const int t = threadIdx.x;
    const int m = t >> 1, s = t & 1;
    float* row = h + (size_t)m * HP + s * 64;
    float sum = 0.f, sq = 0.f;
    #pragma unroll
    for (int q = 0; q < 16; ++q) {
        float4 v = *reinterpret_cast<const float4*>(row + q * 4);
        sum += v.x + v.y + v.z + v.w;
        sq  += v.x * v.x + v.y * v.y + v.z * v.z + v.w * v.w;
    }
    sum += __shfl_xor_sync(0xffffffffu, sum, 1);
    sq  += __shfl_xor_sync(0xffffffffu, sq , 1);
    const float mu  = sum * (1.f / Cc);
    const float var = sq * (1.f / Cc) - mu * mu;
    const float rs  = rsqrtf(var + 1e-5f);
    #pragma unroll
    for (int q = 0; q < 16; ++q) {
        float4 v = *reinterpret_cast<float4*>(row + q * 4);
        const int c = s * 64 + q * 4;
        v.x = (v.x - mu) * rs * g[c + 0] + b[c + 0];
        v.y = (v.y - mu) * rs * g[c + 1] + b[c + 1];
        v.z = (v.z - mu) * rs * g[c + 2] + b[c + 2];
        v.w = (v.w - mu) * rs * g[c + 3] + b[c + 3];
        *reinterpret_cast<float4*>(row + q * 4) = v;
    }
}

// ---------------- K1: LN1 + edge MLPs + gate ---------------------------------
__global__ __launch_bounds__(256, 1) void k1_kernel(
    const float* __restrict__ X, const void* __restrict__ mask,
    const float* __restrict__ ln1g, const float* __restrict__ ln1b,
    const float* __restrict__ lw1, const float* __restrict__ lb1,
    const float* __restrict__ lw2, const float* __restrict__ lb2,
    const float* __restrict__ rw1, const float* __restrict__ rb1,
    const float* __restrict__ rw2, const float* __restrict__ rb2,
    const float* __restrict__ sw_, const float* __restrict__ sb_)
{
    extern __shared__ float smem[];
    float* h   = smem;                         // [128][HP]
    float* u   = smem + 128 * HP;              // [128][HP]
    u64*   Wt2 = reinterpret_cast<u64*>(smem + 2 * 128 * HP);  // [128][WROW]
    __shared__ float msk[128];

    const int t  = threadIdx.x;
    const int t0 = blockIdx.x * 128;

    // load X tile (128x128) as float4, coalesced
    {
        const float4* X4 = reinterpret_cast<const float4*>(X + (size_t)t0 * Cc);
        #pragma unroll
        for (int r = 0; r < 16; ++r) {
            int idx = t + r * 256;
            int m = idx >> 5, q = idx & 31;
            *reinterpret_cast<float4*>(h + (size_t)m * HP + q * 4) = X4[idx];
        }
    }
    if (t < 128) {
        const int mode = g_mask_mode;
        const int tk = t0 + t;
        float mv;
        if (mode == 0)      mv = (((const int*)mask)[tk] != 0) ? 1.f : 0.f;
        else if (mode == 1) mv = (((const unsigned char*)mask)[tk] != 0) ? 1.f : 0.f;
        else                mv = (((const float*)mask)[tk] != 0.f) ? 1.f : 0.f;
        msk[t] = mv;
    }
    __syncthreads();

    ln128(h, ln1g, ln1b);
    __syncthreads();

    u64* gA = reinterpret_cast<u64*>(g_A);
    u64* gB = reinterpret_cast<u64*>(g_B);
    u64* gG = reinterpret_cast<u64*>(g_G);

    // left edge: u = sigmoid(h@lw1^T+lb1); A = mask*(u@lw2^T+lb2)
    lin128x2<true , false, false, true , false>(h, Wt2, lw1, lb1, u, nullptr, nullptr, nullptr, t0);
    lin128x2<false, true , false, false, true >(u, Wt2, lw2, lb2, nullptr, gA, msk, nullptr, t0);
    // right edge
    lin128x2<true , false, false, true , false>(h, Wt2, rw1, rb1, u, nullptr, nullptr, nullptr, t0);
    lin128x2<false, true , false, false, true >(u, Wt2, rw2, rb2, nullptr, gB, msk, nullptr, t0);
    // skip gate
    lin128x2<true , false, false, false, true >(h, Wt2, sw_, sb_, nullptr, gG, nullptr, nullptr, t0);
}

// ---------------- K2: triangle einsum, packed f32x2 --------------------------
__global__ __launch_bounds__(256, 1) void k2_kernel()
{
    const int cp = threadIdx.x;                 // channel pair 0..63
    const int ty = threadIdx.y, tz = threadIdx.z;

    const int sb  = blockIdx.x;                 // 0..1023
    const int st  = sb >> 6, w = sb & 63;       // 16 supertiles of 64 blocks
    const int sti = st >> 2, stj = st & 3;      // 4x4 supertile grid
    const int bi  = sti * 8 + (w >> 3);
    const int bj  = stj * 8 + (w & 7);
    const int i0  = bi * 16 + ty * 8;
    const int j0  = bj * 16 + tz * 8;

    const u64* __restrict__ A2 = reinterpret_cast<const u64*>(g_A);
    const u64* __restrict__ B2 = reinterpret_cast<const u64*>(g_B);

    u64 acc[8][8];
    #pragma unroll
    for (int ii = 0; ii < 8; ++ii)
        #pragma unroll
        for (int jj = 0; jj < 8; ++jj) acc[ii][jj] = 0ull;

    const u64* ap = A2 + (size_t)i0 * Nn * 64 + cp;
    const u64* bp = B2 + (size_t)j0 * Nn * 64 + cp;

    for (int k = 0; k < Nn; ++k) {
        u64 a[8], b[8];
        #pragma unroll
        for (int ii = 0; ii < 8; ++ii) a[ii] = ap[(size_t)ii * Nn * 64 + (size_t)k * 64];
        #pragma unroll
        for (int jj = 0; jj < 8; ++jj) b[jj] = bp[(size_t)jj * Nn * 64 + (size_t)k * 64];
        #pragma unroll
        for (int ii = 0; ii < 8; ++ii)
            #pragma unroll
            for (int jj = 0; jj < 8; ++jj)
                acc[ii][jj] = ffma2(a[ii], b[jj], acc[ii][jj]);
    }

    u64* __restrict__ T2 = reinterpret_cast<u64*>(g_T);
    #pragma unroll
    for (int ii = 0; ii < 8; ++ii)
        #pragma unroll
        for (int jj = 0; jj < 8; ++jj)
            T2[((size_t)(i0 + ii) * Nn + (j0 + jj)) * 64 + cp] = acc[ii][jj];
}

// ---------------- K3: LN2 + combine linear + gate ----------------------------
__global__ __launch_bounds__(256, 1) void k3_kernel(
    const float* __restrict__ ln2g, const float* __restrict__ ln2b,
    const float* __restrict__ cw, const float* __restrict__ cb,
    float* __restrict__ Y)
{
    extern __shared__ float smem[];
    float* h   = smem;                                  // [128][HP]
    u64*   Wt2 = reinterpret_cast<u64*>(smem + 128 * HP);

    const int t  = threadIdx.x;
    const int t0 = blockIdx.x * 128;

    {
        const float4* T4 = reinterpret_cast<const float4*>(g_T + (size_t)t0 * Cc);
        #pragma unroll
        for (int r = 0; r < 16; ++r) {
            int idx = t + r * 256;
            int m = idx >> 5, q = idx & 31;
            *reinterpret_cast<float4*>(h + (size_t)m * HP + q * 4) = T4[idx];
        }
    }
    __syncthreads();

    ln128(h, ln2g, ln2b);
    __syncthreads();

    // Y = (LN(T) @ cw^T + cb) * G
    lin128x2<false, false, true, false, true>(
        h, Wt2, cw, cb, nullptr, reinterpret_cast<u64*>(Y), nullptr,
        reinterpret_cast<const u64*>(g_G), t0);
}

// ---------------- launch ------------------------------------------------------
extern "C" void kernel_launch(void* const* d_in, const int* in_sizes, int n_in,
                              void* d_out, int out_size)
{
    (void)in_sizes; (void)n_in; (void)out_size;
    const float* X    = (const float*)d_in[0];
    const void*  mask = d_in[1];
    const float* ln1g = (const float*)d_in[2];
    const float* ln1b = (const float*)d_in[3];
    const float* lw1  = (const float*)d_in[4];
    const float* lb1  = (const float*)d_in[5];
    const float* lw2  = (const float*)d_in[6];
    const float* lb2  = (const float*)d_in[7];
    const float* rw1  = (const float*)d_in[8];
    const float* rb1  = (const float*)d_in[9];
    const float* rw2  = (const float*)d_in[10];
    const float* rb2  = (const float*)d_in[11];
    const float* sw_  = (const float*)d_in[12];
    const float* sb_  = (const float*)d_in[13];
    const float* ln2g = (const float*)d_in[14];
    const float* ln2b = (const float*)d_in[15];
    const float* cw   = (const float*)d_in[16];
    const float* cb   = (const float*)d_in[17];
    float* Y = (float*)d_out;

    const int smem1 = (2 * 128 * HP) * 4 + 128 * WROW * 8;   // 202752 B
    const int smem3 = (128 * HP) * 4 + 128 * WROW * 8;       // 135168 B
    cudaFuncSetAttribute(k1_kernel, cudaFuncAttributeMaxDynamicSharedMemorySize, smem1);
    cudaFuncSetAttribute(k3_kernel, cudaFuncAttributeMaxDynamicSharedMemorySize, smem3);

    kdetect<<<1, 256>>>((const unsigned int*)mask);
    k1_kernel<<<NPOS / 128, 256, smem1>>>(X, mask, ln1g, ln1b, lw1, lb1, lw2, lb2,
                                          rw1, rb1, rw2, rb2, sw_, sb_);
    dim3 b2(64, 2, 2);
    k2_kernel<<<1024, b2>>>();
    k3_kernel<<<NPOS / 128, 256, smem3>>>(ln2g, ln2b, cw, cb, Y);
}